// round 15
// baseline (speedup 1.0000x reference)
#include <cuda_runtime.h>
#include <math.h>

#define RR 16
#define GG 4096
#define KN 8
#define HID 64
#define BATCH 4
#define NPTS 4096
#define NBIN 4096   // 16^3 bins per batch

typedef unsigned long long u64;

// ---------------- device scratch (no allocations allowed) ----------------
__device__ int    g_knn[BATCH * GG * KN];
__device__ float  g_vol[BATCH * HID * GG];
__device__ float  g_t1[BATCH * HID * GG];
__device__ float  g_t2[BATCH * HID * GG];
__device__ float  g_vol2[BATCH * HID * 512];
__device__ float  g_ps[128 * HID];
__device__ float  g_pq[128 * HID];
__device__ float  g_sum_bc[BATCH * HID];
__device__ float  g_ssq_bc[BATCH * HID];
// KNN binning
__device__ int    g_boff[BATCH * NBIN + 1];
__device__ float4 g_pts[BATCH * NPTS];   // x,y,z,pn  (CSR order)
__device__ int    g_pidx[BATCH * NPTS];  // point index within batch
__device__ short  g_shell[1331];         // packed (dx+5)|(dy+5)<<4|(dz+5)<<8, shells r=0..5

// ---------------- packed fp32x2 helpers (sm_103a FFMA2) ----------------
__device__ __forceinline__ void ffma2(u64& d, u64 a, u64 b) {
    asm("fma.rn.f32x2 %0, %1, %2, %0;" : "+l"(d) : "l"(a), "l"(b));
}
__device__ __forceinline__ u64 pack2(float lo, float hi) {
    u64 r; asm("mov.b64 %0, {%1, %2};" : "=l"(r) : "f"(lo), "f"(hi)); return r;
}
__device__ __forceinline__ void unpack2(float& lo, float& hi, u64 v) {
    asm("mov.b64 {%0, %1}, %2;" : "=f"(lo), "=f"(hi) : "l"(v));
}

__device__ __forceinline__ float gelu_f(float v) {
    float a = 0.7978845608028654f * (v + 0.044715f * v * v * v);
    float t = 1.0f - __fdividef(2.0f, __expf(2.0f * a) + 1.0f);
    return 0.5f * v * (1.0f + t);
}

// linspace(-1,1,16) bit-exact: rn(-1 + rn(i * rn(2/15)))
__device__ __forceinline__ float grid_coord(int i) {
    const float delta = 2.0f / 15.0f;
    return __fadd_rn(-1.0f, __fmul_rn((float)i, delta));
}

__device__ __forceinline__ int bin_of(float v) {
    int q = (int)floorf((v + 1.0f) * 8.0f);
    return min(15, max(0, q));
}

// ---------------- fused binning: count + scan + scatter, 1 block per batch --
__global__ void bin_build(const float* __restrict__ pos) {
    __shared__ int s_cnt[NBIN];        // counts -> cursors
    __shared__ int s_wsum[32];
    __shared__ int s_rc[6];
    int b = blockIdx.x, t = threadIdx.x;        // 1024 threads
    int lane = t & 31, wid = t >> 5;

    for (int i = t; i < NBIN; i += 1024) s_cnt[i] = 0;
    if (t < 6) s_rc[t] = 0;
    __syncthreads();

    float px[4], py[4], pz[4], pw[4]; int pb[4];
#pragma unroll
    for (int u = 0; u < 4; u++) {
        int n = t + u * 1024;
        const float* p = pos + (b * NPTS + n) * 3;
        float x = p[0], y = p[1], z = p[2];
        px[u] = x; py[u] = y; pz[u] = z;
        pw[u] = __fadd_rn(__fadd_rn(__fmul_rn(x, x), __fmul_rn(y, y)), __fmul_rn(z, z));
        pb[u] = (bin_of(x) * 16 + bin_of(y)) * 16 + bin_of(z);
        atomicAdd(&s_cnt[pb[u]], 1);
    }
    __syncthreads();

    int base = t * 4;
    int c0 = s_cnt[base + 0], c1 = s_cnt[base + 1], c2 = s_cnt[base + 2], c3 = s_cnt[base + 3];
    int sum = c0 + c1 + c2 + c3;
    int pref = sum;
#pragma unroll
    for (int off = 1; off < 32; off <<= 1) {
        int v = __shfl_up_sync(0xffffffffu, pref, off);
        if (lane >= off) pref += v;
    }
    int excl = pref - sum;
    if (lane == 31) s_wsum[wid] = pref;
    __syncthreads();
    if (wid == 0) {
        int v = s_wsum[lane];
        int p2 = v;
#pragma unroll
        for (int off = 1; off < 32; off <<= 1) {
            int w = __shfl_up_sync(0xffffffffu, p2, off);
            if (lane >= off) p2 += w;
        }
        s_wsum[lane] = p2 - v;
    }
    __syncthreads();
    int o0 = s_wsum[wid] + excl;
    int o1 = o0 + c0, o2 = o1 + c1, o3 = o2 + c2;
    int gbase = b * NPTS;
    g_boff[b * NBIN + base + 0] = gbase + o0;
    g_boff[b * NBIN + base + 1] = gbase + o1;
    g_boff[b * NBIN + base + 2] = gbase + o2;
    g_boff[b * NBIN + base + 3] = gbase + o3;
    s_cnt[base + 0] = o0; s_cnt[base + 1] = o1; s_cnt[base + 2] = o2; s_cnt[base + 3] = o3;
    if (b == 0 && t == 0) g_boff[BATCH * NBIN] = BATCH * NPTS;
    __syncthreads();

#pragma unroll
    for (int u = 0; u < 4; u++) {
        int slot = gbase + atomicAdd(&s_cnt[pb[u]], 1);
        g_pts[slot] = make_float4(px[u], py[u], pz[u], pw[u]);
        g_pidx[slot] = t + u * 1024;
    }

    if (b == 0) {
        for (int i = t; i < 1331; i += 1024) {
            int dz = i / 121 - 5;
            int rem = i % 121;
            int dy = rem / 11 - 5;
            int dx = rem % 11 - 5;
            int r = max(abs(dx), max(abs(dy), abs(dz)));
            int d2 = 2 * r - 1;
            int start = (r == 0) ? 0 : d2 * d2 * d2;
            int slot = start + atomicAdd(&s_rc[r], 1);
            g_shell[slot] = (short)((dx + 5) | ((dy + 5) << 4) | ((dz + 5) << 8));
        }
    }
}

// ---------------- KNN: WARP per voxel, table-driven shells -----------------
__global__ void knn_search() {
    int b = blockIdx.y;
    int warp = threadIdx.x >> 5, lane = threadIdx.x & 31;
    int g = blockIdx.x * 8 + warp;
    int ix = g >> 8, iy = (g >> 4) & 15, iz = g & 15;
    float gx = grid_coord(ix), gy = grid_coord(iy), gz = grid_coord(iz);
    float gn = __fadd_rn(__fadd_rn(__fmul_rn(gx, gx), __fmul_rn(gy, gy)), __fmul_rn(gz, gz));

    float bd[KN]; int bi[KN];
#pragma unroll
    for (int j = 0; j < KN; j++) { bd[j] = 3e38f; bi[j] = 0x7fffffff; }

    int binbase = b * NBIN;
    const int SHS[7] = {0, 1, 27, 125, 343, 729, 1331};

    bool done = false;
    for (int r = 0; r <= 5 && !done; r++) {
        for (int i = SHS[r] + lane; i < SHS[r + 1]; i += 32) {
            int pk = g_shell[i];
            int xx = ix + (pk & 15) - 5;
            int yy = iy + ((pk >> 4) & 15) - 5;
            int zz = iz + ((pk >> 8) & 15) - 5;
            if ((unsigned)xx > 15u || (unsigned)yy > 15u || (unsigned)zz > 15u) continue;
            int bin = binbase + (xx * 16 + yy) * 16 + zz;
            int s = g_boff[bin], e = g_boff[bin + 1];
            for (int j = s; j < e; j++) {
                float4 p = g_pts[j];
                int ii = g_pidx[j];
                float ee = fmaf(gz, p.z, fmaf(gy, p.y, __fmul_rn(gx, p.x)));
                float d = __fsub_rn(__fadd_rn(gn, p.w), __fmul_rn(2.0f, ee));
                if (d < bd[KN - 1] || (d == bd[KN - 1] && ii < bi[KN - 1])) {
                    bool pr[KN];
#pragma unroll
                    for (int q = 0; q < KN; q++)
                        pr[q] = (d < bd[q]) || (d == bd[q] && ii < bi[q]);
#pragma unroll
                    for (int q = KN - 1; q >= 1; q--) {
                        bd[q] = pr[q - 1] ? bd[q - 1] : (pr[q] ? d : bd[q]);
                        bi[q] = pr[q - 1] ? bi[q - 1] : (pr[q] ? ii : bi[q]);
                    }
                    if (pr[0]) { bd[0] = d; bi[0] = ii; }
                }
            }
        }
        if (r >= 1) {
            float rb = 0.125f * (float)r;
            float th = rb * rb - 4e-5f;
            int n = 0;
#pragma unroll
            for (int j = 0; j < KN; j++) n += (bd[j] < th) ? 1 : 0;
            n = __reduce_add_sync(0xffffffffu, n);
            if (n >= 8) done = true;
        }
    }
    for (int r = 6; r <= 15 && !done; r++) {   // fallback; not taken for uniform data
        int side = 2 * r + 1, tot = side * side * side;
        for (int i = lane; i < tot; i += 32) {
            int dz = i / (side * side) - r;
            int rem = i % (side * side);
            int dy = rem / side - r;
            int dx = rem % side - r;
            if (max(abs(dx), max(abs(dy), abs(dz))) != r) continue;
            int xx = ix + dx, yy = iy + dy, zz = iz + dz;
            if ((unsigned)xx > 15u || (unsigned)yy > 15u || (unsigned)zz > 15u) continue;
            int bin = binbase + (xx * 16 + yy) * 16 + zz;
            int s = g_boff[bin], e = g_boff[bin + 1];
            for (int j = s; j < e; j++) {
                float4 p = g_pts[j];
                int ii = g_pidx[j];
                float ee = fmaf(gz, p.z, fmaf(gy, p.y, __fmul_rn(gx, p.x)));
                float d = __fsub_rn(__fadd_rn(gn, p.w), __fmul_rn(2.0f, ee));
                if (d < bd[KN - 1] || (d == bd[KN - 1] && ii < bi[KN - 1])) {
                    bool pr[KN];
#pragma unroll
                    for (int q = 0; q < KN; q++)
                        pr[q] = (d < bd[q]) || (d == bd[q] && ii < bi[q]);
#pragma unroll
                    for (int q = KN - 1; q >= 1; q--) {
                        bd[q] = pr[q - 1] ? bd[q - 1] : (pr[q] ? d : bd[q]);
                        bi[q] = pr[q - 1] ? bi[q - 1] : (pr[q] ? ii : bi[q]);
                    }
                    if (pr[0]) { bd[0] = d; bi[0] = ii; }
                }
            }
        }
        float rb = 0.125f * (float)r;
        float th = rb * rb - 4e-5f;
        int n = 0;
#pragma unroll
        for (int j = 0; j < KN; j++) n += (bd[j] < th) ? 1 : 0;
        n = __reduce_add_sync(0xffffffffu, n);
        if (n >= 8) done = true;
    }

    int knn_out = (b * GG + g) * KN;
    for (int sel = 0; sel < KN; sel++) {
        float v = bd[0]; int vi = bi[0]; int vl = lane;
#pragma unroll
        for (int off = 16; off; off >>= 1) {
            float ov = __shfl_xor_sync(0xffffffffu, v, off);
            int   oi = __shfl_xor_sync(0xffffffffu, vi, off);
            int   ol = __shfl_xor_sync(0xffffffffu, vl, off);
            if (ov < v || (ov == v && oi < vi)) { v = ov; vi = oi; vl = ol; }
        }
        if (lane == 0) g_knn[knn_out + sel] = vi;
        if (lane == vl) {
#pragma unroll
            for (int j = 0; j < KN - 1; j++) { bd[j] = bd[j + 1]; bi[j] = bi[j + 1]; }
            bd[KN - 1] = 3e38f; bi[KN - 1] = 0x7fffffff;
        }
    }
}

// ---------------- Edge (BipartiteConv + update net): warp per voxel --------
__global__ void edge_kernel(const float* __restrict__ pos, const float* __restrict__ xin,
                            const float* __restrict__ pe_w1, const float* __restrict__ pe_b1,
                            const float* __restrict__ pe_w2, const float* __restrict__ pe_b2,
                            const float* __restrict__ f_w, const float* __restrict__ f_b,
                            const float* __restrict__ up_w, const float* __restrict__ up_b) {
    __shared__ __align__(16) float s_w2[HID * HID];
    __shared__ __align__(16) float s_up[HID * HID];
    __shared__ float s_pw1[3 * HID], s_pb1[HID], s_pb2[HID], s_fw[3 * HID], s_fb[HID], s_ub[HID];
    __shared__ __align__(16) float s_h1[8][KN][HID];
    __shared__ __align__(16) float s_agg[8][HID];

    int t = threadIdx.x;
    for (int i = t; i < HID * HID; i += 256) { s_w2[i] = pe_w2[i]; s_up[i] = up_w[i]; }
    if (t < 192) { s_pw1[t] = pe_w1[t]; s_fw[t] = f_w[t]; }
    if (t < 64)  { s_pb1[t] = pe_b1[t]; s_pb2[t] = pe_b2[t]; s_fb[t] = f_b[t]; s_ub[t] = up_b[t]; }
    __syncthreads();

    int warp = t >> 5, lane = t & 31;
    int b = blockIdx.y;
    int g = blockIdx.x * 8 + warp;
    float gx = grid_coord(g >> 8);
    float gy = grid_coord((g >> 4) & 15);
    float gz = grid_coord(g & 15);

    int o0 = 2 * lane, o1 = o0 + 1;
    float fm0[KN], fm1[KN];

#pragma unroll
    for (int k = 0; k < KN; k++) {
        int nidx = g_knn[(b * GG + g) * KN + k];
        const float* pp = pos + (b * NPTS + nidx) * 3;
        float rx = pp[0] - gx, ry = pp[1] - gy, rz = pp[2] - gz;
        const float* xp = xin + (b * NPTS + nidx) * 3;
        float f0 = xp[0], f1 = xp[1], f2 = xp[2];

        float h0 = s_pb1[o0] + rx * s_pw1[o0] + ry * s_pw1[64 + o0] + rz * s_pw1[128 + o0];
        float h1 = s_pb1[o1] + rx * s_pw1[o1] + ry * s_pw1[64 + o1] + rz * s_pw1[128 + o1];
        s_h1[warp][k][o0] = gelu_f(h0);
        s_h1[warp][k][o1] = gelu_f(h1);

        fm0[k] = s_fb[o0] + f0 * s_fw[o0] + f1 * s_fw[64 + o0] + f2 * s_fw[128 + o0];
        fm1[k] = s_fb[o1] + f0 * s_fw[o1] + f1 * s_fw[64 + o1] + f2 * s_fw[128 + o1];
    }
    __syncwarp();

    float a0 = 0.0f, a1 = 0.0f;
    for (int k = 0; k < KN; k++) {
        u64 pe01 = pack2(s_pb2[o0], s_pb2[o1]);
#pragma unroll
        for (int c = 0; c < HID; c += 4) {
            float4 av = *(const float4*)&s_h1[warp][k][c];
            u64 w0 = *(const u64*)&s_w2[(c + 0) * HID + o0];
            u64 w1 = *(const u64*)&s_w2[(c + 1) * HID + o0];
            u64 w2 = *(const u64*)&s_w2[(c + 2) * HID + o0];
            u64 w3 = *(const u64*)&s_w2[(c + 3) * HID + o0];
            ffma2(pe01, pack2(av.x, av.x), w0);
            ffma2(pe01, pack2(av.y, av.y), w1);
            ffma2(pe01, pack2(av.z, av.z), w2);
            ffma2(pe01, pack2(av.w, av.w), w3);
        }
        float pe0, pe1; unpack2(pe0, pe1, pe01);
        a0 = fmaf(pe0, fm0[k], a0);
        a1 = fmaf(pe1, fm1[k], a1);
    }
    a0 *= (1.0f / KN);
    a1 *= (1.0f / KN);
    s_agg[warp][o0] = a0;
    s_agg[warp][o1] = a1;
    __syncwarp();

    u64 u01 = pack2(s_ub[o0], s_ub[o1]);
#pragma unroll
    for (int c = 0; c < HID; c += 4) {
        float4 av = *(const float4*)&s_agg[warp][c];
        u64 w0 = *(const u64*)&s_up[(c + 0) * HID + o0];
        u64 w1 = *(const u64*)&s_up[(c + 1) * HID + o0];
        u64 w2 = *(const u64*)&s_up[(c + 2) * HID + o0];
        u64 w3 = *(const u64*)&s_up[(c + 3) * HID + o0];
        ffma2(u01, pack2(av.x, av.x), w0);
        ffma2(u01, pack2(av.y, av.y), w1);
        ffma2(u01, pack2(av.z, av.z), w2);
        ffma2(u01, pack2(av.w, av.w), w3);
    }
    float u0, u1; unpack2(u0, u1, u01);
    u0 = gelu_f(u0);
    u1 = gelu_f(u1);

    int iz = g & 15, iy = (g >> 4) & 15, ix = g >> 8;
    int sp = iz * 256 + iy * 16 + ix;
    g_vol[(b * HID + o0) * GG + sp] = u0;
    g_vol[(b * HID + o1) * GG + sp] = u1;
}

// ---------------- direct 3x3x3 conv, SAME, 64->64, y-split for occupancy ---
// Block = (z-plane, y-slab of YS rows, batch, og-group). Thread = one (y,x).
template <int DIM, int CI, int OG, int YS, bool BNRELU>
__global__ void conv_kernel(const float* __restrict__ in, const float* __restrict__ w,
                            const float* __restrict__ bias, float* __restrict__ out,
                            int npart, float inv_n) {
    constexpr int P = DIM + 2;
    constexpr int YP = YS + 2;
    constexpr int NYS = DIM / YS;
    constexpr int NT = YS * DIM;
    constexpr int NW = NT / 32;
    __shared__ float s_in[3 * CI * YP * P];
    __shared__ __align__(16) float s_w[27 * CI * OG];
    __shared__ float s_mean[HID], s_inv[HID];
    __shared__ float s_tS[128], s_tQ[128];
    __shared__ float sred_s[NW][OG], sred_q[NW][OG];

    int bx = blockIdx.x;
    int z = bx / NYS, ysub = bx % NYS;
    int y0 = ysub * YS;
    int b = blockIdx.y, o0 = blockIdx.z * OG;
    int t = threadIdx.x;
    int yl = t / DIM, x = t % DIM;

    if (BNRELU) {
        if (NT >= 2 * HID) {
            if (t < 2 * HID) {
                int c = t & (HID - 1), h = t >> 6;
                int half = npart >> 1;
                float S = 0.0f, Q = 0.0f;
                for (int p = h * half; p < (h + 1) * half; p++) {
                    S += g_ps[p * HID + c]; Q += g_pq[p * HID + c];
                }
                s_tS[t] = S; s_tQ[t] = Q;
            }
            __syncthreads();
            if (t < HID) {
                float S = s_tS[t] + s_tS[t + HID];
                float Q = s_tQ[t] + s_tQ[t + HID];
                float m = S * inv_n;
                s_mean[t] = m;
                s_inv[t] = rsqrtf(Q * inv_n - m * m + 1e-5f);
            }
        } else {
            if (t < HID) {
                float S = 0.0f, Q = 0.0f;
                for (int p = 0; p < npart; p++) { S += g_ps[p * HID + t]; Q += g_pq[p * HID + t]; }
                float m = S * inv_n;
                s_mean[t] = m;
                s_inv[t] = rsqrtf(Q * inv_n - m * m + 1e-5f);
            }
        }
        __syncthreads();
    }

    u64 accP[OG / 2];
#pragma unroll
    for (int q = 0; q < OG / 2; q++) accP[q] = pack2(bias[o0 + 2 * q], bias[o0 + 2 * q + 1]);

    for (int cc = 0; cc < HID; cc += CI) {
        __syncthreads();
        for (int i = t; i < 3 * CI * YP * P; i += NT) {
            int xx = i % P; int r = i / P; int yy = r % YP; r /= YP;
            int ci = r % CI; int pz = r / CI;
            int gz_ = z + pz - 1, gy_ = y0 + yy - 1, gx_ = xx - 1;
            float v = 0.0f;
            if (gz_ >= 0 && gz_ < DIM && gy_ >= 0 && gy_ < DIM && gx_ >= 0 && gx_ < DIM) {
                v = in[(((b * HID + cc + ci) * DIM + gz_) * DIM + gy_) * DIM + gx_];
                if (BNRELU) v = fmaxf(0.0f, (v - s_mean[cc + ci]) * s_inv[cc + ci]);
            }
            s_in[i] = v;
        }
        for (int i = t; i < 27 * CI * OG; i += NT) {
            int og = i % OG; int r = i / OG; int ci = r % CI; int tap = r / CI;
            s_w[i] = w[((o0 + og) * HID + cc + ci) * 27 + tap];
        }
        __syncthreads();

#pragma unroll 1
        for (int tap = 0; tap < 27; tap++) {
            int kd = tap / 9, kh = (tap / 3) % 3, kw = tap % 3;
            const float* ap = &s_in[((kd * CI) * YP + yl + kh) * P + x + kw];
            const ulonglong2* wp4 = (const ulonglong2*)&s_w[tap * CI * OG];
#pragma unroll
            for (int ci = 0; ci < CI; ci++) {
                float a = ap[ci * YP * P];
                u64 a2 = pack2(a, a);
#pragma unroll
                for (int q = 0; q < OG / 4; q++) {
                    ulonglong2 wv = wp4[ci * (OG / 4) + q];
                    ffma2(accP[2 * q + 0], a2, wv.x);
                    ffma2(accP[2 * q + 1], a2, wv.y);
                }
            }
        }
    }

    float acc[OG];
#pragma unroll
    for (int q = 0; q < OG / 2; q++) unpack2(acc[2 * q], acc[2 * q + 1], accP[q]);

    int spatial = DIM * DIM * DIM;
#pragma unroll
    for (int q = 0; q < OG; q++)
        out[(b * HID + o0 + q) * spatial + (z * DIM + (y0 + yl)) * DIM + x] = acc[q];

    int warp = t >> 5, lane = t & 31;
#pragma unroll
    for (int q = 0; q < OG; q++) {
        float s = acc[q], qq = acc[q] * acc[q];
#pragma unroll
        for (int off = 16; off; off >>= 1) {
            s += __shfl_xor_sync(0xffffffffu, s, off);
            qq += __shfl_xor_sync(0xffffffffu, qq, off);
        }
        if (lane == 0) { sred_s[warp][q] = s; sred_q[warp][q] = qq; }
    }
    __syncthreads();
    if (t < OG) {
        float S = 0.0f, Q = 0.0f;
#pragma unroll
        for (int wv = 0; wv < NW; wv++) { S += sred_s[wv][t]; Q += sred_q[wv][t]; }
        int pblk = bx * BATCH + b;
        g_ps[pblk * HID + o0 + t] = S;
        g_pq[pblk * HID + o0 + t] = Q;
    }
}

// ---------------- block0: stats prologue (128 partials) + residual + pool --
__global__ void resid_pool_kernel(const float* __restrict__ vol, const float* __restrict__ t2) {
    __shared__ float sS[128], sQ[128], s_mi[2];
    int c = blockIdx.x, b = blockIdx.y, t = threadIdx.x;  // 512 threads
    if (t < 128) { sS[t] = g_ps[t * HID + c]; sQ[t] = g_pq[t * HID + c]; }
    __syncthreads();
    if (t == 0) {
        float S = 0.0f, Q = 0.0f;
        for (int j = 0; j < 128; j++) { S += sS[j]; Q += sQ[j]; }
        float m = S * (1.0f / 16384.0f);
        s_mi[0] = m;
        s_mi[1] = rsqrtf(Q * (1.0f / 16384.0f) - m * m + 1e-5f);
    }
    __syncthreads();
    float m = s_mi[0], iv = s_mi[1];
    int z = t >> 6, y = (t >> 3) & 7, x = t & 7;
    const float* vb = vol + (b * HID + c) * 4096;
    const float* tb = t2 + (b * HID + c) * 4096;
    float best = 0.0f;
#pragma unroll
    for (int dz = 0; dz < 2; dz++)
#pragma unroll
        for (int dy = 0; dy < 2; dy++)
#pragma unroll
            for (int dx = 0; dx < 2; dx++) {
                int idx = ((2 * z + dz) * 16 + 2 * y + dy) * 16 + 2 * x + dx;
                float v = fmaxf(0.0f, vb[idx] + (tb[idx] - m) * iv);
                best = fmaxf(best, v);
            }
    g_vol2[(b * HID + c) * 512 + t] = best;
}

// ---------------- block1: stats prologue + residual + relu + sums ----------
__global__ void resid_sum_kernel(const float* __restrict__ vol2, const float* __restrict__ t2) {
    __shared__ float sS[32], sQ[32], s_mi[2];
    int c = blockIdx.x, b = blockIdx.y, t = threadIdx.x;  // 512 threads
    if (t < 32) { sS[t] = g_ps[t * HID + c]; sQ[t] = g_pq[t * HID + c]; }
    __syncthreads();
    if (t == 0) {
        float S = 0.0f, Q = 0.0f;
        for (int j = 0; j < 32; j++) { S += sS[j]; Q += sQ[j]; }
        float m = S * (1.0f / 2048.0f);
        s_mi[0] = m;
        s_mi[1] = rsqrtf(Q * (1.0f / 2048.0f) - m * m + 1e-5f);
    }
    __syncthreads();
    float m = s_mi[0], iv = s_mi[1];
    float v = fmaxf(0.0f, vol2[(b * HID + c) * 512 + t] + (t2[(b * HID + c) * 512 + t] - m) * iv);
    float s = v, q = v * v;
#pragma unroll
    for (int off = 16; off; off >>= 1) {
        s += __shfl_xor_sync(0xffffffffu, s, off);
        q += __shfl_xor_sync(0xffffffffu, q, off);
    }
    __shared__ float ss[16], sq[16];
    int warp = t >> 5, lane = t & 31;
    if (lane == 0) { ss[warp] = s; sq[warp] = q; }
    __syncthreads();
    if (t == 0) {
        float S = 0.0f, Q = 0.0f;
        for (int j = 0; j < 16; j++) { S += ss[j]; Q += sq[j]; }
        g_sum_bc[b * HID + c] = S;
        g_ssq_bc[b * HID + c] = Q;
    }
}

// ---------------- final BN + affine + spatial mean + linear head ----------
__global__ void head_kernel(const float* __restrict__ on_g, const float* __restrict__ on_b,
                            const float* __restrict__ ro_w, const float* __restrict__ ro_b,
                            float* __restrict__ out) {
    __shared__ float pooled[BATCH][HID];
    int t = threadIdx.x;  // 64 threads
    if (t < HID) {
        float S = 0.0f, Q = 0.0f;
        for (int b = 0; b < BATCH; b++) { S += g_sum_bc[b * HID + t]; Q += g_ssq_bc[b * HID + t]; }
        float n = (float)(BATCH * 512);
        float m = S / n;
        float var = Q / n - m * m;
        float iv = rsqrtf(var + 1e-5f);
        for (int b = 0; b < BATCH; b++)
            pooled[b][t] = (g_sum_bc[b * HID + t] * (1.0f / 512.0f) - m) * iv * on_g[t] + on_b[t];
    }
    __syncthreads();
    if (t < 64) {
        int b = t >> 4, j = t & 15;
        float s = ro_b[j];
        for (int c = 0; c < HID; c++) s = fmaf(pooled[b][c], ro_w[c * 16 + j], s);
        out[b * 16 + j] = s;
    }
}

// ---------------- launch ----------------
extern "C" void kernel_launch(void* const* d_in, const int* in_sizes, int n_in,
                              void* d_out, int out_size) {
    const float* pos   = (const float*)d_in[0];
    const float* xin   = (const float*)d_in[1];
    const float* pe_w1 = (const float*)d_in[2];
    const float* pe_b1 = (const float*)d_in[3];
    const float* pe_w2 = (const float*)d_in[4];
    const float* pe_b2 = (const float*)d_in[5];
    const float* f_w   = (const float*)d_in[6];
    const float* f_b   = (const float*)d_in[7];
    const float* up_w  = (const float*)d_in[8];
    const float* up_b  = (const float*)d_in[9];
    const float* conv_w = (const float*)d_in[10];  // [2,2,64,64,3,3,3]
    const float* conv_b = (const float*)d_in[11];  // [2,2,64]
    const float* on_g  = (const float*)d_in[12];
    const float* on_b  = (const float*)d_in[13];
    const float* ro_w  = (const float*)d_in[14];
    const float* ro_b  = (const float*)d_in[15];
    float* out = (float*)d_out;

    float *t1, *t2, *vol, *vol2;
    cudaGetSymbolAddress((void**)&t1, g_t1);
    cudaGetSymbolAddress((void**)&t2, g_t2);
    cudaGetSymbolAddress((void**)&vol, g_vol);
    cudaGetSymbolAddress((void**)&vol2, g_vol2);

    const int WSTRIDE = HID * HID * 27;

    bin_build<<<BATCH, 1024>>>(pos);
    knn_search<<<dim3(512, BATCH), 256>>>();

    edge_kernel<<<dim3(512, BATCH), 256>>>(pos, xin, pe_w1, pe_b1, pe_w2, pe_b2,
                                           f_w, f_b, up_w, up_b);

    // block 0 @ 16^3 : y-split (YS=8) -> 32 x-blocks x 4 batch x 4 og = 512 blocks
    conv_kernel<16, 4, 16, 8, false><<<dim3(32, BATCH, 4), 128>>>(
        vol, conv_w + 0 * WSTRIDE, conv_b + 0 * HID, t1, 0, 0.0f);
    conv_kernel<16, 4, 16, 8, true><<<dim3(32, BATCH, 4), 128>>>(
        t1, conv_w + 1 * WSTRIDE, conv_b + 1 * HID, t2, 128, 1.0f / 16384.0f);
    resid_pool_kernel<<<dim3(64, BATCH), 512>>>(vol, t2);

    // block 1 @ 8^3 (no y-split)
    conv_kernel<8, 8, 16, 8, false><<<dim3(8, BATCH, 4), 64>>>(
        vol2, conv_w + 2 * WSTRIDE, conv_b + 2 * HID, t1, 0, 0.0f);
    conv_kernel<8, 8, 16, 8, true><<<dim3(8, BATCH, 4), 64>>>(
        t1, conv_w + 3 * WSTRIDE, conv_b + 3 * HID, t2, 32, 1.0f / 2048.0f);
    resid_sum_kernel<<<dim3(64, BATCH), 512>>>(vol2, t2);

    head_kernel<<<1, 64>>>(on_g, on_b, ro_w, ro_b, out);
}

// round 17
// speedup vs baseline: 1.2837x; 1.2837x over previous
#include <cuda_runtime.h>
#include <math.h>

#define RR 16
#define GG 4096
#define KN 8
#define HID 64
#define BATCH 4
#define NPTS 4096
#define NBIN 4096   // 16^3 bins per batch

typedef unsigned long long u64;

// ---------------- device scratch (no allocations allowed) ----------------
__device__ int    g_knn[BATCH * GG * KN];
__device__ float  g_vol[BATCH * HID * GG];
__device__ float  g_t1[BATCH * HID * GG];
__device__ float  g_t2[BATCH * HID * GG];
__device__ float  g_vol2[BATCH * HID * 512];
__device__ float  g_ps[128 * HID];
__device__ float  g_pq[128 * HID];
__device__ float  g_sum_bc[BATCH * HID];
__device__ float  g_ssq_bc[BATCH * HID];
// KNN binning
__device__ int    g_boff[BATCH * NBIN + 1];
__device__ float4 g_pts[BATCH * NPTS];   // x,y,z,pn  (CSR order)
__device__ int    g_pidx[BATCH * NPTS];  // point index within batch
__device__ short  g_shell[1331];         // packed (dx+5)|(dy+5)<<4|(dz+5)<<8, shells r=0..5

// ---------------- packed fp32x2 helpers (sm_103a FFMA2) ----------------
__device__ __forceinline__ void ffma2(u64& d, u64 a, u64 b) {
    asm("fma.rn.f32x2 %0, %1, %2, %0;" : "+l"(d) : "l"(a), "l"(b));
}
__device__ __forceinline__ u64 pack2(float lo, float hi) {
    u64 r; asm("mov.b64 %0, {%1, %2};" : "=l"(r) : "f"(lo), "f"(hi)); return r;
}
__device__ __forceinline__ void unpack2(float& lo, float& hi, u64 v) {
    asm("mov.b64 {%0, %1}, %2;" : "=f"(lo), "=f"(hi) : "l"(v));
}

__device__ __forceinline__ float gelu_f(float v) {
    float a = 0.7978845608028654f * (v + 0.044715f * v * v * v);
    float t = 1.0f - __fdividef(2.0f, __expf(2.0f * a) + 1.0f);
    return 0.5f * v * (1.0f + t);
}

// linspace(-1,1,16) bit-exact: rn(-1 + rn(i * rn(2/15)))
__device__ __forceinline__ float grid_coord(int i) {
    const float delta = 2.0f / 15.0f;
    return __fadd_rn(-1.0f, __fmul_rn((float)i, delta));
}

__device__ __forceinline__ int bin_of(float v) {
    int q = (int)floorf((v + 1.0f) * 8.0f);
    return min(15, max(0, q));
}

// ---------------- fused binning: count + scan + scatter, 1 block per batch --
__global__ void bin_build(const float* __restrict__ pos) {
    __shared__ int s_cnt[NBIN];        // counts -> cursors
    __shared__ int s_wsum[32];
    __shared__ int s_rc[6];
    int b = blockIdx.x, t = threadIdx.x;        // 1024 threads
    int lane = t & 31, wid = t >> 5;

    for (int i = t; i < NBIN; i += 1024) s_cnt[i] = 0;
    if (t < 6) s_rc[t] = 0;
    __syncthreads();

    float px[4], py[4], pz[4], pw[4]; int pb[4];
#pragma unroll
    for (int u = 0; u < 4; u++) {
        int n = t + u * 1024;
        const float* p = pos + (b * NPTS + n) * 3;
        float x = p[0], y = p[1], z = p[2];
        px[u] = x; py[u] = y; pz[u] = z;
        pw[u] = __fadd_rn(__fadd_rn(__fmul_rn(x, x), __fmul_rn(y, y)), __fmul_rn(z, z));
        pb[u] = (bin_of(x) * 16 + bin_of(y)) * 16 + bin_of(z);
        atomicAdd(&s_cnt[pb[u]], 1);
    }
    __syncthreads();

    int base = t * 4;
    int c0 = s_cnt[base + 0], c1 = s_cnt[base + 1], c2 = s_cnt[base + 2], c3 = s_cnt[base + 3];
    int sum = c0 + c1 + c2 + c3;
    int pref = sum;
#pragma unroll
    for (int off = 1; off < 32; off <<= 1) {
        int v = __shfl_up_sync(0xffffffffu, pref, off);
        if (lane >= off) pref += v;
    }
    int excl = pref - sum;
    if (lane == 31) s_wsum[wid] = pref;
    __syncthreads();
    if (wid == 0) {
        int v = s_wsum[lane];
        int p2 = v;
#pragma unroll
        for (int off = 1; off < 32; off <<= 1) {
            int w = __shfl_up_sync(0xffffffffu, p2, off);
            if (lane >= off) p2 += w;
        }
        s_wsum[lane] = p2 - v;
    }
    __syncthreads();
    int o0 = s_wsum[wid] + excl;
    int o1 = o0 + c0, o2 = o1 + c1, o3 = o2 + c2;
    int gbase = b * NPTS;
    g_boff[b * NBIN + base + 0] = gbase + o0;
    g_boff[b * NBIN + base + 1] = gbase + o1;
    g_boff[b * NBIN + base + 2] = gbase + o2;
    g_boff[b * NBIN + base + 3] = gbase + o3;
    s_cnt[base + 0] = o0; s_cnt[base + 1] = o1; s_cnt[base + 2] = o2; s_cnt[base + 3] = o3;
    if (b == 0 && t == 0) g_boff[BATCH * NBIN] = BATCH * NPTS;
    __syncthreads();

#pragma unroll
    for (int u = 0; u < 4; u++) {
        int slot = gbase + atomicAdd(&s_cnt[pb[u]], 1);
        g_pts[slot] = make_float4(px[u], py[u], pz[u], pw[u]);
        g_pidx[slot] = t + u * 1024;
    }

    if (b == 0) {
        for (int i = t; i < 1331; i += 1024) {
            int dz = i / 121 - 5;
            int rem = i % 121;
            int dy = rem / 11 - 5;
            int dx = rem % 11 - 5;
            int r = max(abs(dx), max(abs(dy), abs(dz)));
            int d2 = 2 * r - 1;
            int start = (r == 0) ? 0 : d2 * d2 * d2;
            int slot = start + atomicAdd(&s_rc[r], 1);
            g_shell[slot] = (short)((dx + 5) | ((dy + 5) << 4) | ((dz + 5) << 8));
        }
    }
}

// ---------------- KNN: WARP per voxel, table-driven shells -----------------
__global__ void knn_search() {
    int b = blockIdx.y;
    int warp = threadIdx.x >> 5, lane = threadIdx.x & 31;
    int g = blockIdx.x * 8 + warp;
    int ix = g >> 8, iy = (g >> 4) & 15, iz = g & 15;
    float gx = grid_coord(ix), gy = grid_coord(iy), gz = grid_coord(iz);
    float gn = __fadd_rn(__fadd_rn(__fmul_rn(gx, gx), __fmul_rn(gy, gy)), __fmul_rn(gz, gz));

    float bd[KN]; int bi[KN];
#pragma unroll
    for (int j = 0; j < KN; j++) { bd[j] = 3e38f; bi[j] = 0x7fffffff; }

    int binbase = b * NBIN;
    const int SHS[7] = {0, 1, 27, 125, 343, 729, 1331};

    bool done = false;
    for (int r = 0; r <= 5 && !done; r++) {
        for (int i = SHS[r] + lane; i < SHS[r + 1]; i += 32) {
            int pk = g_shell[i];
            int xx = ix + (pk & 15) - 5;
            int yy = iy + ((pk >> 4) & 15) - 5;
            int zz = iz + ((pk >> 8) & 15) - 5;
            if ((unsigned)xx > 15u || (unsigned)yy > 15u || (unsigned)zz > 15u) continue;
            int bin = binbase + (xx * 16 + yy) * 16 + zz;
            int s = g_boff[bin], e = g_boff[bin + 1];
            for (int j = s; j < e; j++) {
                float4 p = g_pts[j];
                int ii = g_pidx[j];
                float ee = fmaf(gz, p.z, fmaf(gy, p.y, __fmul_rn(gx, p.x)));
                float d = __fsub_rn(__fadd_rn(gn, p.w), __fmul_rn(2.0f, ee));
                if (d < bd[KN - 1] || (d == bd[KN - 1] && ii < bi[KN - 1])) {
                    bool pr[KN];
#pragma unroll
                    for (int q = 0; q < KN; q++)
                        pr[q] = (d < bd[q]) || (d == bd[q] && ii < bi[q]);
#pragma unroll
                    for (int q = KN - 1; q >= 1; q--) {
                        bd[q] = pr[q - 1] ? bd[q - 1] : (pr[q] ? d : bd[q]);
                        bi[q] = pr[q - 1] ? bi[q - 1] : (pr[q] ? ii : bi[q]);
                    }
                    if (pr[0]) { bd[0] = d; bi[0] = ii; }
                }
            }
        }
        if (r >= 1) {
            float rb = 0.125f * (float)r;
            float th = rb * rb - 4e-5f;
            int n = 0;
#pragma unroll
            for (int j = 0; j < KN; j++) n += (bd[j] < th) ? 1 : 0;
            n = __reduce_add_sync(0xffffffffu, n);
            if (n >= 8) done = true;
        }
    }
    for (int r = 6; r <= 15 && !done; r++) {   // fallback; not taken for uniform data
        int side = 2 * r + 1, tot = side * side * side;
        for (int i = lane; i < tot; i += 32) {
            int dz = i / (side * side) - r;
            int rem = i % (side * side);
            int dy = rem / side - r;
            int dx = rem % side - r;
            if (max(abs(dx), max(abs(dy), abs(dz))) != r) continue;
            int xx = ix + dx, yy = iy + dy, zz = iz + dz;
            if ((unsigned)xx > 15u || (unsigned)yy > 15u || (unsigned)zz > 15u) continue;
            int bin = binbase + (xx * 16 + yy) * 16 + zz;
            int s = g_boff[bin], e = g_boff[bin + 1];
            for (int j = s; j < e; j++) {
                float4 p = g_pts[j];
                int ii = g_pidx[j];
                float ee = fmaf(gz, p.z, fmaf(gy, p.y, __fmul_rn(gx, p.x)));
                float d = __fsub_rn(__fadd_rn(gn, p.w), __fmul_rn(2.0f, ee));
                if (d < bd[KN - 1] || (d == bd[KN - 1] && ii < bi[KN - 1])) {
                    bool pr[KN];
#pragma unroll
                    for (int q = 0; q < KN; q++)
                        pr[q] = (d < bd[q]) || (d == bd[q] && ii < bi[q]);
#pragma unroll
                    for (int q = KN - 1; q >= 1; q--) {
                        bd[q] = pr[q - 1] ? bd[q - 1] : (pr[q] ? d : bd[q]);
                        bi[q] = pr[q - 1] ? bi[q - 1] : (pr[q] ? ii : bi[q]);
                    }
                    if (pr[0]) { bd[0] = d; bi[0] = ii; }
                }
            }
        }
        float rb = 0.125f * (float)r;
        float th = rb * rb - 4e-5f;
        int n = 0;
#pragma unroll
        for (int j = 0; j < KN; j++) n += (bd[j] < th) ? 1 : 0;
        n = __reduce_add_sync(0xffffffffu, n);
        if (n >= 8) done = true;
    }

    int knn_out = (b * GG + g) * KN;
    for (int sel = 0; sel < KN; sel++) {
        float v = bd[0]; int vi = bi[0]; int vl = lane;
#pragma unroll
        for (int off = 16; off; off >>= 1) {
            float ov = __shfl_xor_sync(0xffffffffu, v, off);
            int   oi = __shfl_xor_sync(0xffffffffu, vi, off);
            int   ol = __shfl_xor_sync(0xffffffffu, vl, off);
            if (ov < v || (ov == v && oi < vi)) { v = ov; vi = oi; vl = ol; }
        }
        if (lane == 0) g_knn[knn_out + sel] = vi;
        if (lane == vl) {
#pragma unroll
            for (int j = 0; j < KN - 1; j++) { bd[j] = bd[j + 1]; bi[j] = bi[j + 1]; }
            bd[KN - 1] = 3e38f; bi[KN - 1] = 0x7fffffff;
        }
    }
}

// ---------------- Edge (BipartiteConv + update net): warp per voxel --------
// pe matmul runs c-outer / k-inner: per-lane weight u64s loaded ONCE per
// c-step and reused across all 8 neighbors (8x fewer weight LDS).
__global__ void edge_kernel(const float* __restrict__ pos, const float* __restrict__ xin,
                            const float* __restrict__ pe_w1, const float* __restrict__ pe_b1,
                            const float* __restrict__ pe_w2, const float* __restrict__ pe_b2,
                            const float* __restrict__ f_w, const float* __restrict__ f_b,
                            const float* __restrict__ up_w, const float* __restrict__ up_b) {
    __shared__ __align__(16) float s_w2[HID * HID];
    __shared__ __align__(16) float s_up[HID * HID];
    __shared__ float s_pw1[3 * HID], s_pb1[HID], s_pb2[HID], s_fw[3 * HID], s_fb[HID], s_ub[HID];
    __shared__ __align__(16) float s_h1[8][KN][HID];
    __shared__ __align__(16) float s_agg[8][HID];

    int t = threadIdx.x;
    for (int i = t; i < HID * HID; i += 256) { s_w2[i] = pe_w2[i]; s_up[i] = up_w[i]; }
    if (t < 192) { s_pw1[t] = pe_w1[t]; s_fw[t] = f_w[t]; }
    if (t < 64)  { s_pb1[t] = pe_b1[t]; s_pb2[t] = pe_b2[t]; s_fb[t] = f_b[t]; s_ub[t] = up_b[t]; }
    __syncthreads();

    int warp = t >> 5, lane = t & 31;
    int b = blockIdx.y;
    int g = blockIdx.x * 8 + warp;
    float gx = grid_coord(g >> 8);
    float gy = grid_coord((g >> 4) & 15);
    float gz = grid_coord(g & 15);

    int o0 = 2 * lane, o1 = o0 + 1;
    float fm0[KN], fm1[KN];

#pragma unroll
    for (int k = 0; k < KN; k++) {
        int nidx = g_knn[(b * GG + g) * KN + k];
        const float* pp = pos + (b * NPTS + nidx) * 3;
        float rx = pp[0] - gx, ry = pp[1] - gy, rz = pp[2] - gz;
        const float* xp = xin + (b * NPTS + nidx) * 3;
        float f0 = xp[0], f1 = xp[1], f2 = xp[2];

        float h0 = s_pb1[o0] + rx * s_pw1[o0] + ry * s_pw1[64 + o0] + rz * s_pw1[128 + o0];
        float h1 = s_pb1[o1] + rx * s_pw1[o1] + ry * s_pw1[64 + o1] + rz * s_pw1[128 + o1];
        s_h1[warp][k][o0] = gelu_f(h0);
        s_h1[warp][k][o1] = gelu_f(h1);

        fm0[k] = s_fb[o0] + f0 * s_fw[o0] + f1 * s_fw[64 + o0] + f2 * s_fw[128 + o0];
        fm1[k] = s_fb[o1] + f0 * s_fw[o1] + f1 * s_fw[64 + o1] + f2 * s_fw[128 + o1];
    }
    __syncwarp();

    u64 pe01[KN];
#pragma unroll
    for (int k = 0; k < KN; k++) pe01[k] = pack2(s_pb2[o0], s_pb2[o1]);

#pragma unroll
    for (int c = 0; c < HID; c += 4) {
        u64 w0 = *(const u64*)&s_w2[(c + 0) * HID + o0];
        u64 w1 = *(const u64*)&s_w2[(c + 1) * HID + o0];
        u64 w2 = *(const u64*)&s_w2[(c + 2) * HID + o0];
        u64 w3 = *(const u64*)&s_w2[(c + 3) * HID + o0];
#pragma unroll
        for (int k = 0; k < KN; k++) {
            float4 av = *(const float4*)&s_h1[warp][k][c];
            ffma2(pe01[k], pack2(av.x, av.x), w0);
            ffma2(pe01[k], pack2(av.y, av.y), w1);
            ffma2(pe01[k], pack2(av.z, av.z), w2);
            ffma2(pe01[k], pack2(av.w, av.w), w3);
        }
    }

    float a0 = 0.0f, a1 = 0.0f;
#pragma unroll
    for (int k = 0; k < KN; k++) {
        float pe0, pe1; unpack2(pe0, pe1, pe01[k]);
        a0 = fmaf(pe0, fm0[k], a0);
        a1 = fmaf(pe1, fm1[k], a1);
    }
    a0 *= (1.0f / KN);
    a1 *= (1.0f / KN);
    s_agg[warp][o0] = a0;
    s_agg[warp][o1] = a1;
    __syncwarp();

    u64 u01 = pack2(s_ub[o0], s_ub[o1]);
#pragma unroll
    for (int c = 0; c < HID; c += 4) {
        float4 av = *(const float4*)&s_agg[warp][c];
        u64 w0 = *(const u64*)&s_up[(c + 0) * HID + o0];
        u64 w1 = *(const u64*)&s_up[(c + 1) * HID + o0];
        u64 w2 = *(const u64*)&s_up[(c + 2) * HID + o0];
        u64 w3 = *(const u64*)&s_up[(c + 3) * HID + o0];
        ffma2(u01, pack2(av.x, av.x), w0);
        ffma2(u01, pack2(av.y, av.y), w1);
        ffma2(u01, pack2(av.z, av.z), w2);
        ffma2(u01, pack2(av.w, av.w), w3);
    }
    float u0, u1; unpack2(u0, u1, u01);
    u0 = gelu_f(u0);
    u1 = gelu_f(u1);

    int iz = g & 15, iy = (g >> 4) & 15, ix = g >> 8;
    int sp = iz * 256 + iy * 16 + ix;
    g_vol[(b * HID + o0) * GG + sp] = u0;
    g_vol[(b * HID + o1) * GG + sp] = u1;
}

// ---------------- direct 3x3x3 conv, SAME, 64->64 ----------------
// XP x-outputs per thread (strided by XT) amortize the broadcast weight
// loads: per (tap,ci) 4 a-wf + 16 w-wf vs 16 fma-cycles -> near fma floor.
template <int DIM, int CI, int OG, int XP, bool BNRELU>
__global__ void conv_kernel(const float* __restrict__ in, const float* __restrict__ w,
                            const float* __restrict__ bias, float* __restrict__ out,
                            int npart, float inv_n) {
    constexpr int P = DIM + 2;
    constexpr int XT = DIM / XP;
    constexpr int NT = DIM * XT;
    constexpr int NW = NT / 32;
    __shared__ float s_in[3 * CI * P * P];
    __shared__ __align__(16) float s_w[27 * CI * OG];
    __shared__ float s_mean[HID], s_inv[HID];
    __shared__ float sred_s[NW][OG], sred_q[NW][OG];

    int z = blockIdx.x, b = blockIdx.y, o0 = blockIdx.z * OG;
    int t = threadIdx.x;
    int y = t / XT, xp = t % XT;

    if (BNRELU) {
        for (int c = t; c < HID; c += NT) {
            float S = 0.0f, Q = 0.0f;
            for (int p = 0; p < npart; p++) { S += g_ps[p * HID + c]; Q += g_pq[p * HID + c]; }
            float m = S * inv_n;
            s_mean[c] = m;
            s_inv[c] = rsqrtf(Q * inv_n - m * m + 1e-5f);
        }
        __syncthreads();
    }

    u64 accP[XP][OG / 2];
#pragma unroll
    for (int u = 0; u < XP; u++)
#pragma unroll
        for (int q = 0; q < OG / 2; q++)
            accP[u][q] = pack2(bias[o0 + 2 * q], bias[o0 + 2 * q + 1]);

    for (int cc = 0; cc < HID; cc += CI) {
        __syncthreads();
        for (int i = t; i < 3 * CI * P * P; i += NT) {
            int xx = i % P; int r = i / P; int yy = r % P; r /= P;
            int ci = r % CI; int pz = r / CI;
            int gz_ = z + pz - 1, gy_ = yy - 1, gx_ = xx - 1;
            float v = 0.0f;
            if (gz_ >= 0 && gz_ < DIM && gy_ >= 0 && gy_ < DIM && gx_ >= 0 && gx_ < DIM) {
                v = in[(((b * HID + cc + ci) * DIM + gz_) * DIM + gy_) * DIM + gx_];
                if (BNRELU) v = fmaxf(0.0f, (v - s_mean[cc + ci]) * s_inv[cc + ci]);
            }
            s_in[i] = v;
        }
        for (int i = t; i < 27 * CI * OG; i += NT) {
            int og = i % OG; int r = i / OG; int ci = r % CI; int tap = r / CI;
            s_w[i] = w[((o0 + og) * HID + cc + ci) * 27 + tap];
        }
        __syncthreads();

#pragma unroll 1
        for (int tap = 0; tap < 27; tap++) {
            int kd = tap / 9, kh = (tap / 3) % 3, kw = tap % 3;
            const float* ap = &s_in[(kd * CI) * P * P + (y + kh) * P + kw];
            const ulonglong2* wp4 = (const ulonglong2*)&s_w[tap * CI * OG];
#pragma unroll
            for (int ci = 0; ci < CI; ci++) {
                u64 a2[XP];
#pragma unroll
                for (int u = 0; u < XP; u++) {
                    float a = ap[ci * P * P + xp + u * XT];
                    a2[u] = pack2(a, a);
                }
#pragma unroll
                for (int q = 0; q < OG / 4; q++) {
                    ulonglong2 wv = wp4[ci * (OG / 4) + q];
#pragma unroll
                    for (int u = 0; u < XP; u++) {
                        ffma2(accP[u][2 * q + 0], a2[u], wv.x);
                        ffma2(accP[u][2 * q + 1], a2[u], wv.y);
                    }
                }
            }
        }
    }

    float acc[XP][OG];
#pragma unroll
    for (int u = 0; u < XP; u++)
#pragma unroll
        for (int q = 0; q < OG / 2; q++)
            unpack2(acc[u][2 * q], acc[u][2 * q + 1], accP[u][q]);

    int spatial = DIM * DIM * DIM;
#pragma unroll
    for (int u = 0; u < XP; u++)
#pragma unroll
        for (int q = 0; q < OG; q++)
            out[(b * HID + o0 + q) * spatial + (z * DIM + y) * DIM + (xp + u * XT)] = acc[u][q];

    int warp = t >> 5, lane = t & 31;
#pragma unroll
    for (int q = 0; q < OG; q++) {
        float s = 0.0f, qq = 0.0f;
#pragma unroll
        for (int u = 0; u < XP; u++) { s += acc[u][q]; qq += acc[u][q] * acc[u][q]; }
#pragma unroll
        for (int off = 16; off; off >>= 1) {
            s += __shfl_xor_sync(0xffffffffu, s, off);
            qq += __shfl_xor_sync(0xffffffffu, qq, off);
        }
        if (lane == 0) { sred_s[warp][q] = s; sred_q[warp][q] = qq; }
    }
    __syncthreads();
    if (t < OG) {
        float S = 0.0f, Q = 0.0f;
#pragma unroll
        for (int wv = 0; wv < NW; wv++) { S += sred_s[wv][t]; Q += sred_q[wv][t]; }
        int pblk = blockIdx.x * BATCH + blockIdx.y;
        g_ps[pblk * HID + o0 + t] = S;
        g_pq[pblk * HID + o0 + t] = Q;
    }
}

// ---------------- block0: stats prologue + residual + relu + maxpool -------
__global__ void resid_pool_kernel(const float* __restrict__ vol, const float* __restrict__ t2) {
    __shared__ float sS[64], sQ[64], s_mi[2];
    int c = blockIdx.x, b = blockIdx.y, t = threadIdx.x;  // 512 threads
    if (t < 64) { sS[t] = g_ps[t * HID + c]; sQ[t] = g_pq[t * HID + c]; }
    __syncthreads();
    if (t == 0) {
        float S = 0.0f, Q = 0.0f;
        for (int j = 0; j < 64; j++) { S += sS[j]; Q += sQ[j]; }
        float m = S * (1.0f / 16384.0f);
        s_mi[0] = m;
        s_mi[1] = rsqrtf(Q * (1.0f / 16384.0f) - m * m + 1e-5f);
    }
    __syncthreads();
    float m = s_mi[0], iv = s_mi[1];
    int z = t >> 6, y = (t >> 3) & 7, x = t & 7;
    const float* vb = vol + (b * HID + c) * 4096;
    const float* tb = t2 + (b * HID + c) * 4096;
    float best = 0.0f;
#pragma unroll
    for (int dz = 0; dz < 2; dz++)
#pragma unroll
        for (int dy = 0; dy < 2; dy++)
#pragma unroll
            for (int dx = 0; dx < 2; dx++) {
                int idx = ((2 * z + dz) * 16 + 2 * y + dy) * 16 + 2 * x + dx;
                float v = fmaxf(0.0f, vb[idx] + (tb[idx] - m) * iv);
                best = fmaxf(best, v);
            }
    g_vol2[(b * HID + c) * 512 + t] = best;
}

// ---------------- block1: stats prologue + residual + relu + sums ----------
__global__ void resid_sum_kernel(const float* __restrict__ vol2, const float* __restrict__ t2) {
    __shared__ float sS[32], sQ[32], s_mi[2];
    int c = blockIdx.x, b = blockIdx.y, t = threadIdx.x;  // 512 threads
    if (t < 32) { sS[t] = g_ps[t * HID + c]; sQ[t] = g_pq[t * HID + c]; }
    __syncthreads();
    if (t == 0) {
        float S = 0.0f, Q = 0.0f;
        for (int j = 0; j < 32; j++) { S += sS[j]; Q += sQ[j]; }
        float m = S * (1.0f / 2048.0f);
        s_mi[0] = m;
        s_mi[1] = rsqrtf(Q * (1.0f / 2048.0f) - m * m + 1e-5f);
    }
    __syncthreads();
    float m = s_mi[0], iv = s_mi[1];
    float v = fmaxf(0.0f, vol2[(b * HID + c) * 512 + t] + (t2[(b * HID + c) * 512 + t] - m) * iv);
    float s = v, q = v * v;
#pragma unroll
    for (int off = 16; off; off >>= 1) {
        s += __shfl_xor_sync(0xffffffffu, s, off);
        q += __shfl_xor_sync(0xffffffffu, q, off);
    }
    __shared__ float ss[16], sq[16];
    int warp = t >> 5, lane = t & 31;
    if (lane == 0) { ss[warp] = s; sq[warp] = q; }
    __syncthreads();
    if (t == 0) {
        float S = 0.0f, Q = 0.0f;
        for (int j = 0; j < 16; j++) { S += ss[j]; Q += sq[j]; }
        g_sum_bc[b * HID + c] = S;
        g_ssq_bc[b * HID + c] = Q;
    }
}

// ---------------- final BN + affine + spatial mean + linear head ----------
__global__ void head_kernel(const float* __restrict__ on_g, const float* __restrict__ on_b,
                            const float* __restrict__ ro_w, const float* __restrict__ ro_b,
                            float* __restrict__ out) {
    __shared__ float pooled[BATCH][HID];
    int t = threadIdx.x;  // 64 threads
    if (t < HID) {
        float S = 0.0f, Q = 0.0f;
        for (int b = 0; b < BATCH; b++) { S += g_sum_bc[b * HID + t]; Q += g_ssq_bc[b * HID + t]; }
        float n = (float)(BATCH * 512);
        float m = S / n;
        float var = Q / n - m * m;
        float iv = rsqrtf(var + 1e-5f);
        for (int b = 0; b < BATCH; b++)
            pooled[b][t] = (g_sum_bc[b * HID + t] * (1.0f / 512.0f) - m) * iv * on_g[t] + on_b[t];
    }
    __syncthreads();
    if (t < 64) {
        int b = t >> 4, j = t & 15;
        float s = ro_b[j];
        for (int c = 0; c < HID; c++) s = fmaf(pooled[b][c], ro_w[c * 16 + j], s);
        out[b * 16 + j] = s;
    }
}

// ---------------- launch ----------------
extern "C" void kernel_launch(void* const* d_in, const int* in_sizes, int n_in,
                              void* d_out, int out_size) {
    const float* pos   = (const float*)d_in[0];
    const float* xin   = (const float*)d_in[1];
    const float* pe_w1 = (const float*)d_in[2];
    const float* pe_b1 = (const float*)d_in[3];
    const float* pe_w2 = (const float*)d_in[4];
    const float* pe_b2 = (const float*)d_in[5];
    const float* f_w   = (const float*)d_in[6];
    const float* f_b   = (const float*)d_in[7];
    const float* up_w  = (const float*)d_in[8];
    const float* up_b  = (const float*)d_in[9];
    const float* conv_w = (const float*)d_in[10];  // [2,2,64,64,3,3,3]
    const float* conv_b = (const float*)d_in[11];  // [2,2,64]
    const float* on_g  = (const float*)d_in[12];
    const float* on_b  = (const float*)d_in[13];
    const float* ro_w  = (const float*)d_in[14];
    const float* ro_b  = (const float*)d_in[15];
    float* out = (float*)d_out;

    float *t1, *t2, *vol, *vol2;
    cudaGetSymbolAddress((void**)&t1, g_t1);
    cudaGetSymbolAddress((void**)&t2, g_t2);
    cudaGetSymbolAddress((void**)&vol, g_vol);
    cudaGetSymbolAddress((void**)&vol2, g_vol2);

    const int WSTRIDE = HID * HID * 27;

    bin_build<<<BATCH, 1024>>>(pos);
    knn_search<<<dim3(512, BATCH), 256>>>();

    edge_kernel<<<dim3(512, BATCH), 256>>>(pos, xin, pe_w1, pe_b1, pe_w2, pe_b2,
                                           f_w, f_b, up_w, up_b);

    // block 0 @ 16^3 : XP=4 register tiling, 64-thread blocks, 256 blocks
    conv_kernel<16, 4, 16, 4, false><<<dim3(16, BATCH, 4), 64>>>(
        vol, conv_w + 0 * WSTRIDE, conv_b + 0 * HID, t1, 0, 0.0f);
    conv_kernel<16, 4, 16, 4, true><<<dim3(16, BATCH, 4), 64>>>(
        t1, conv_w + 1 * WSTRIDE, conv_b + 1 * HID, t2, 64, 1.0f / 16384.0f);
    resid_pool_kernel<<<dim3(64, BATCH), 512>>>(vol, t2);

    // block 1 @ 8^3
    conv_kernel<8, 8, 16, 1, false><<<dim3(8, BATCH, 4), 64>>>(
        vol2, conv_w + 2 * WSTRIDE, conv_b + 2 * HID, t1, 0, 0.0f);
    conv_kernel<8, 8, 16, 1, true><<<dim3(8, BATCH, 4), 64>>>(
        t1, conv_w + 3 * WSTRIDE, conv_b + 3 * HID, t2, 32, 1.0f / 2048.0f);
    resid_sum_kernel<<<dim3(64, BATCH), 512>>>(vol2, t2);

    head_kernel<<<1, 64>>>(on_g, on_b, ro_w, ro_b, out);
}